// round 13
// baseline (speedup 1.0000x reference)
#include <cuda_runtime.h>

#define KCODES 256
#define DIM 32
#define TPB 128
#define NTILES 4096          // 524288 / 128 tokens per CTA
#define ASTRIDE 33           // padded A row stride (words) -> conflict-free frags

typedef unsigned u32;
typedef unsigned long long u64;

__global__ void vq_zero_counts(float* counts) {
    counts[threadIdx.x] = 0.0f;
}

__device__ __forceinline__ u32 to_tf32(float f) {
    u32 u;
    asm("cvt.rna.tf32.f32 %0, %1;" : "=r"(u) : "f"(f));
    return u;
}

__device__ __forceinline__ void mma_tf32(float d[4], const u32 a[4], u32 b0, u32 b1) {
    asm volatile(
        "mma.sync.aligned.m16n8k8.row.col.f32.tf32.tf32.f32 "
        "{%0,%1,%2,%3},{%4,%5,%6,%7},{%8,%9},{%0,%1,%2,%3};"
        : "+f"(d[0]), "+f"(d[1]), "+f"(d[2]), "+f"(d[3])
        : "r"(a[0]), "r"(a[1]), "r"(a[2]), "r"(a[3]), "r"(b0), "r"(b1));
}

__global__ __launch_bounds__(TPB, 4) void vq_tc(
    const float* __restrict__ x,
    const float* __restrict__ cb,
    float* __restrict__ out_rot,
    float* __restrict__ out_idx,
    float* __restrict__ out_counts)
{
    extern __shared__ __align__(16) u32 smem_dyn[];
    u64* Bq = reinterpret_cast<u64*>(smem_dyn);   // 32c x 4ks x 32lane u64 = 32 KB
    u32* As = smem_dyn + 8192;                    // 128 x 33 words = 16896 B

    __shared__ float c2_s[KCODES];
    __shared__ float hist[KCODES];
    __shared__ float best1[TPB];
    __shared__ float best2[TPB];
    __shared__ int   bestk[TPB];

    const int tid  = threadIdx.x;
    const int lane = tid & 31;
    const int wid  = tid >> 5;
    const int gid  = lane >> 2;
    const int tig  = lane & 3;
    const int m0   = wid * 32;

    const long long tok0 = (long long)blockIdx.x * TPB;

    // ---- Stage A: token tid; exact x2 (sequential, reference order); tf32 to smem ----
    float xr[DIM];
    float x2;
    {
        const float4* xp = reinterpret_cast<const float4*>(x + (tok0 + tid) * DIM);
        #pragma unroll
        for (int j = 0; j < 8; j++) {
            float4 v = __ldg(xp + j);
            xr[4*j+0] = v.x; xr[4*j+1] = v.y; xr[4*j+2] = v.z; xr[4*j+3] = v.w;
        }
        float s = 0.0f;
        #pragma unroll
        for (int d = 0; d < DIM; d++)
            s = __fadd_rn(s, __fmul_rn(xr[d], xr[d]));
        x2 = s;
        #pragma unroll
        for (int d = 0; d < DIM; d++)
            As[tid * ASTRIDE + d] = to_tf32(xr[d]);
    }

    // ---- Stage B: exact c2 (2 rows/thread); Bq fragment-paired tf32 (32 entries/thread) ----
    #pragma unroll
    for (int rr = 0; rr < 2; rr++) {
        const int r = tid + rr * TPB;
        const float4* src = reinterpret_cast<const float4*>(cb + r * DIM);
        float row[DIM];
        #pragma unroll
        for (int j = 0; j < 8; j++) {
            float4 v = __ldg(src + j);
            row[4*j+0] = v.x; row[4*j+1] = v.y; row[4*j+2] = v.z; row[4*j+3] = v.w;
        }
        float s = 0.0f;
        #pragma unroll
        for (int d = 0; d < DIM; d++)
            s = __fadd_rn(s, __fmul_rn(row[d], row[d]));
        c2_s[r] = s;
        hist[r] = 0.0f;
    }
    #pragma unroll
    for (int ee = 0; ee < 32; ee++) {
        const int e  = tid + ee * TPB;        // 4096 entries
        const int le = e & 31;
        const int ks = (e >> 5) & 3;
        const int c  = e >> 7;
        const int r  = c * 8 + (le >> 2);
        const int k0 = ks * 8 + (le & 3);
        u32 w0 = to_tf32(__ldg(cb + r * DIM + k0));
        u32 w1 = to_tf32(__ldg(cb + r * DIM + k0 + 4));
        Bq[e] = (u64)w0 | ((u64)w1 << 32);
    }
    __syncthreads();

    // ---- A fragments: 2 m-tiles x 4 k-steps x 4 regs ----
    u32 afr[2][4][4];
    #pragma unroll
    for (int mt = 0; mt < 2; mt++) {
        const int r0 = m0 + mt * 16 + gid;
        #pragma unroll
        for (int ks = 0; ks < 4; ks++) {
            const int k0 = ks * 8 + tig;
            afr[mt][ks][0] = As[ r0      * ASTRIDE + k0];
            afr[mt][ks][1] = As[(r0 + 8) * ASTRIDE + k0];
            afr[mt][ks][2] = As[ r0      * ASTRIDE + k0 + 4];
            afr[mt][ks][3] = As[(r0 + 8) * ASTRIDE + k0 + 4];
        }
    }

    // ---- Single pass: per-slice top-2 of s = c2 - 2*dot (+ argmin index) ----
    float m1[4], m2[4];
    int   kk[4];
    #pragma unroll
    for (int i = 0; i < 4; i++) { m1[i] = 3.4e38f; m2[i] = 3.4e38f; kk[i] = 0; }

    #pragma unroll 1
    for (int c = 0; c < 32; c++) {
        u32 b[4][2];
        #pragma unroll
        for (int ks = 0; ks < 4; ks++) {
            u64 bp = Bq[(c * 4 + ks) * 32 + lane];
            b[ks][0] = (u32)bp; b[ks][1] = (u32)(bp >> 32);
        }
        const int col0 = c * 8 + tig * 2;
        const float c2a = c2_s[col0];
        const float c2b = c2_s[col0 + 1];

        #pragma unroll
        for (int mt = 0; mt < 2; mt++) {
            float dA[4] = {0.f, 0.f, 0.f, 0.f};
            float dB[4] = {0.f, 0.f, 0.f, 0.f};
            mma_tf32(dA, afr[mt][0], b[0][0], b[0][1]);
            mma_tf32(dB, afr[mt][2], b[2][0], b[2][1]);
            mma_tf32(dA, afr[mt][1], b[1][0], b[1][1]);
            mma_tf32(dB, afr[mt][3], b[3][0], b[3][1]);
            float s0 = __fmaf_rn(-2.0f, __fadd_rn(dA[0], dB[0]), c2a);
            float s1 = __fmaf_rn(-2.0f, __fadd_rn(dA[1], dB[1]), c2b);
            float s2 = __fmaf_rn(-2.0f, __fadd_rn(dA[2], dB[2]), c2a);
            float s3 = __fmaf_rn(-2.0f, __fadd_rn(dA[3], dB[3]), c2b);

            // pair-wise top-2 update (keeps m1 = min, m2 = exact second-min)
            #define TOP2(i, sa, sb)                                              \
            {                                                                    \
                float pmin = fminf(sa, sb);                                      \
                float pmax = fmaxf(sa, sb);                                      \
                int   pk   = (sb < sa) ? (col0 + 1) : col0;                      \
                if (pmin < m1[i]) { m2[i] = fminf(m1[i], pmax); m1[i] = pmin; kk[i] = pk; } \
                else              { m2[i] = fminf(m2[i], pmin); }                \
            }
            TOP2(2 * mt,     s0, s1)
            TOP2(2 * mt + 1, s2, s3)
            #undef TOP2
        }
    }

    // ---- Quad reduce (merge top-2 multisets across tig lanes) ----
    #pragma unroll
    for (int i = 0; i < 4; i++) {
        #pragma unroll
        for (int off = 1; off <= 2; off <<= 1) {
            float om1 = __shfl_xor_sync(0xFFFFFFFFu, m1[i], off);
            float om2 = __shfl_xor_sync(0xFFFFFFFFu, m2[i], off);
            int   ok  = __shfl_xor_sync(0xFFFFFFFFu, kk[i], off);
            if (om1 < m1[i]) { m2[i] = fminf(om2, m1[i]); m1[i] = om1; kk[i] = ok; }
            else             { m2[i] = fminf(m2[i], om1); }
        }
    }
    if (tig == 0) {
        #pragma unroll
        for (int i = 0; i < 4; i++) {
            const int t = m0 + (i >> 1) * 16 + (i & 1) * 8 + gid;
            best1[t] = m1[i]; best2[t] = m2[i]; bestk[t] = kk[i];
        }
    }
    __syncthreads();

    // ---- Decide: fast path (provable unique argmin) or cooperative exact fallback ----
    int bi = bestk[tid];
    {
        const float bm1 = best1[tid];
        const float bm2 = best2[tid];
        const float twotau = __fmaf_rn(sqrtf(x2), 1e-4f, 4e-5f);
        const bool fb = !(bm2 > bm1 + twotau);

        unsigned fmask = __ballot_sync(0xFFFFFFFFu, fb);
        while (fmask) {
            const int src = __ffs(fmask) - 1;
            fmask &= fmask - 1;
            // all 32 lanes cooperatively do the exact scan for token (m0 + src)
            const float x2s = __shfl_sync(0xFFFFFFFFu, x2, src);
            float xs[DIM];
            {
                const float4* xp = reinterpret_cast<const float4*>(
                    x + (tok0 + m0 + src) * DIM);
                #pragma unroll
                for (int j = 0; j < 8; j++) {
                    float4 v = __ldg(xp + j);
                    xs[4*j+0] = v.x; xs[4*j+1] = v.y; xs[4*j+2] = v.z; xs[4*j+3] = v.w;
                }
            }
            // lane handles codes [lane*8, lane*8+8): ascending k, strict <
            float bl = 3.4e38f;
            int   bk = 0;
            #pragma unroll 1
            for (int j = 0; j < 8; j++) {
                const int k = lane * 8 + j;
                const float4* qr = reinterpret_cast<const float4*>(cb + k * DIM);
                float dot = 0.0f;
                #pragma unroll
                for (int jj = 0; jj < 8; jj++) {
                    float4 q4 = __ldg(qr + jj);
                    dot = __fmaf_rn(xs[4*jj+0], q4.x, dot);
                    dot = __fmaf_rn(xs[4*jj+1], q4.y, dot);
                    dot = __fmaf_rn(xs[4*jj+2], q4.z, dot);
                    dot = __fmaf_rn(xs[4*jj+3], q4.w, dot);
                }
                float d2 = __fadd_rn(__fadd_rn(x2s, __fmul_rn(-2.0f, dot)), c2_s[k]);
                if (d2 < bl) { bl = d2; bk = k; }
            }
            // lexicographic (d2, k) min across lanes == global first-index argmin
            #pragma unroll
            for (int off = 16; off >= 1; off >>= 1) {
                float ob  = __shfl_xor_sync(0xFFFFFFFFu, bl, off);
                int   okk = __shfl_xor_sync(0xFFFFFFFFu, bk, off);
                if (ob < bl || (ob == bl && okk < bk)) { bl = ob; bk = okk; }
            }
            if (lane == src) bi = bk;
        }
    }

    // ---- Epilogue: histogram + rotation-trick output ----
    atomicAdd(&hist[bi], 1.0f);
    {
        float qv[DIM];
        const float4* qrow = reinterpret_cast<const float4*>(cb + bi * DIM);
        #pragma unroll
        for (int j = 0; j < 8; j++) {
            float4 v = __ldg(qrow + j);
            qv[4*j+0] = v.x; qv[4*j+1] = v.y; qv[4*j+2] = v.z; qv[4*j+3] = v.w;
        }
        float q2 = 0.f, dotq = 0.f;
        #pragma unroll
        for (int d = 0; d < DIM; d++) {
            q2   = __fmaf_rn(qv[d], qv[d], q2);
            dotq = __fmaf_rn(xr[d], qv[d], dotq);
        }
        const float eps = 1e-6f;
        float inx = 1.0f / fmaxf(sqrtf(x2), eps);
        float inq = 1.0f / fmaxf(sqrtf(q2), eps);
        float u2  = x2 * inx * inx;
        float qh2 = q2 * inq * inq;
        float uq  = dotq * inx * inq;
        float w2  = u2 + qh2 + 2.0f * uq;
        float iw  = 1.0f / fmaxf(sqrtf(w2), eps);
        float ew  = (x2 * inx + dotq * inq) * iw;
        float eu  = x2 * inx;
        float a   = -2.0f * ew * iw;
        float s1  = 1.0f + a * inx;
        float s2  = (a + 2.0f * eu) * inq;

        float4* rp = reinterpret_cast<float4*>(out_rot + (tok0 + tid) * DIM);
        #pragma unroll
        for (int j = 0; j < 8; j++) {
            float4 v;
            v.x = xr[4*j+0] * s1 + qv[4*j+0] * s2;
            v.y = xr[4*j+1] * s1 + qv[4*j+1] * s2;
            v.z = xr[4*j+2] * s1 + qv[4*j+2] * s2;
            v.w = xr[4*j+3] * s1 + qv[4*j+3] * s2;
            rp[j] = v;
        }
        out_idx[tok0 + tid] = (float)bi;
    }

    // ---- Flush histogram ----
    __syncthreads();
    #pragma unroll
    for (int rr = 0; rr < 2; rr++)
        atomicAdd(&out_counts[tid + rr * TPB], hist[tid + rr * TPB]);
}

extern "C" void kernel_launch(void* const* d_in, const int* in_sizes, int n_in,
                              void* d_out, int out_size) {
    const float* x  = (const float*)d_in[0];
    const float* cb = (const float*)d_in[1];
    float* out = (float*)d_out;

    const int N = in_sizes[0] / DIM;            // 524288
    float* rot    = out;
    float* idx    = out + (size_t)N * DIM;
    float* counts = idx + N;

    const int dyn = 32768 + TPB * ASTRIDE * 4;  // Bq + As = 49664 B
    cudaFuncSetAttribute(vq_tc, cudaFuncAttributeMaxDynamicSharedMemorySize, dyn);
    vq_zero_counts<<<1, KCODES>>>(counts);
    vq_tc<<<NTILES, TPB, dyn>>>(x, cb, rot, idx, counts);
}

// round 14
// speedup vs baseline: 1.9215x; 1.9215x over previous
#include <cuda_runtime.h>

#define KCODES 256
#define DIM 32
#define TPB 128
#define NTILES 4096          // 524288 / 128 tokens per CTA
#define ASTRIDE 33           // padded A row stride (words)
#define CANDCAP 6

typedef unsigned u32;
typedef unsigned long long u64;

__global__ void vq_zero_counts(float* counts) {
    counts[threadIdx.x] = 0.0f;
}

__device__ __forceinline__ u32 to_tf32(float f) {
    u32 u;
    asm("cvt.rna.tf32.f32 %0, %1;" : "=r"(u) : "f"(f));
    return u;
}

__device__ __forceinline__ void mma_tf32(float d[4], const u32 a[4], u32 b0, u32 b1) {
    asm volatile(
        "mma.sync.aligned.m16n8k8.row.col.f32.tf32.tf32.f32 "
        "{%0,%1,%2,%3},{%4,%5,%6,%7},{%8,%9},{%0,%1,%2,%3};"
        : "+f"(d[0]), "+f"(d[1]), "+f"(d[2]), "+f"(d[3])
        : "r"(a[0]), "r"(a[1]), "r"(a[2]), "r"(a[3]), "r"(b0), "r"(b1));
}

// Shared s-computation for both passes: identical op order -> bitwise-equal s.
// Split accumulators (ks0-1 / ks2-3) -> 4 independent 2-deep MMA chains.
__device__ __forceinline__ void calc_s(
    const u64 bp[4], const u32 afr[2][4][4],
    float c2a, float c2b, float s[2][4])
{
    u32 b0[4], b1[4];
    #pragma unroll
    for (int ks = 0; ks < 4; ks++) { b0[ks] = (u32)bp[ks]; b1[ks] = (u32)(bp[ks] >> 32); }
    #pragma unroll
    for (int mt = 0; mt < 2; mt++) {
        float dA[4] = {0.f, 0.f, 0.f, 0.f};
        float dB[4] = {0.f, 0.f, 0.f, 0.f};
        mma_tf32(dA, afr[mt][0], b0[0], b1[0]);
        mma_tf32(dB, afr[mt][2], b0[2], b1[2]);
        mma_tf32(dA, afr[mt][1], b0[1], b1[1]);
        mma_tf32(dB, afr[mt][3], b0[3], b1[3]);
        s[mt][0] = __fmaf_rn(-2.0f, __fadd_rn(dA[0], dB[0]), c2a);
        s[mt][1] = __fmaf_rn(-2.0f, __fadd_rn(dA[1], dB[1]), c2b);
        s[mt][2] = __fmaf_rn(-2.0f, __fadd_rn(dA[2], dB[2]), c2a);
        s[mt][3] = __fmaf_rn(-2.0f, __fadd_rn(dA[3], dB[3]), c2b);
    }
}

__global__ __launch_bounds__(TPB, 4) void vq_tc(
    const float* __restrict__ x,
    const float* __restrict__ cb,
    float* __restrict__ out_rot,
    float* __restrict__ out_idx,
    float* __restrict__ out_counts)
{
    extern __shared__ __align__(16) u32 smem_dyn[];
    u64* Bq = reinterpret_cast<u64*>(smem_dyn);   // 32c x 4ks x 32lane u64 = 32 KB
    u32* As = smem_dyn + 8192;                    // 128 x 33 words

    __shared__ float c2_s[KCODES];
    __shared__ float hist[KCODES];
    __shared__ float best_s[TPB];
    __shared__ float thr_s[TPB];
    __shared__ int   cand_cnt[TPB];
    __shared__ int   cand[TPB * CANDCAP];

    const int tid  = threadIdx.x;
    const int lane = tid & 31;
    const int wid  = tid >> 5;
    const int gid  = lane >> 2;
    const int tig  = lane & 3;
    const int m0   = wid * 32;

    const long long tok0 = (long long)blockIdx.x * TPB;

    // ---- Stage A: token tid; exact x2 (sequential, reference order); tf32 copy ----
    float xr[DIM];
    float x2;
    {
        const float4* xp = reinterpret_cast<const float4*>(x + (tok0 + tid) * DIM);
        #pragma unroll
        for (int j = 0; j < 8; j++) {
            float4 v = __ldg(xp + j);
            xr[4*j+0] = v.x; xr[4*j+1] = v.y; xr[4*j+2] = v.z; xr[4*j+3] = v.w;
        }
        float s = 0.0f;
        #pragma unroll
        for (int d = 0; d < DIM; d++)
            s = __fadd_rn(s, __fmul_rn(xr[d], xr[d]));
        x2 = s;
        #pragma unroll
        for (int d = 0; d < DIM; d++)
            As[tid * ASTRIDE + d] = to_tf32(xr[d]);
    }

    // ---- Stage B: exact c2 (2 rows/thread); Bq fragment-paired tf32 ----
    #pragma unroll
    for (int rr = 0; rr < 2; rr++) {
        const int r = tid + rr * TPB;
        const float4* src = reinterpret_cast<const float4*>(cb + r * DIM);
        float row[DIM];
        #pragma unroll
        for (int j = 0; j < 8; j++) {
            float4 v = __ldg(src + j);
            row[4*j+0] = v.x; row[4*j+1] = v.y; row[4*j+2] = v.z; row[4*j+3] = v.w;
        }
        float s = 0.0f;
        #pragma unroll
        for (int d = 0; d < DIM; d++)
            s = __fadd_rn(s, __fmul_rn(row[d], row[d]));
        c2_s[r] = s;
        hist[r] = 0.0f;
    }
    #pragma unroll
    for (int ee = 0; ee < 32; ee++) {
        const int e  = tid + ee * TPB;        // 4096 entries
        const int le = e & 31;
        const int ks = (e >> 5) & 3;
        const int c  = e >> 7;
        const int r  = c * 8 + (le >> 2);
        const int k0 = ks * 8 + (le & 3);
        u32 w0 = to_tf32(__ldg(cb + r * DIM + k0));
        u32 w1 = to_tf32(__ldg(cb + r * DIM + k0 + 4));
        Bq[e] = (u64)w0 | ((u64)w1 << 32);
    }
    __syncthreads();

    // ---- A fragments: 2 m-tiles x 4 k-steps x 4 regs ----
    u32 afr[2][4][4];
    #pragma unroll
    for (int mt = 0; mt < 2; mt++) {
        const int r0 = m0 + mt * 16 + gid;
        #pragma unroll
        for (int ks = 0; ks < 4; ks++) {
            const int k0 = ks * 8 + tig;
            afr[mt][ks][0] = As[ r0      * ASTRIDE + k0];
            afr[mt][ks][1] = As[(r0 + 8) * ASTRIDE + k0];
            afr[mt][ks][2] = As[ r0      * ASTRIDE + k0 + 4];
            afr[mt][ks][3] = As[(r0 + 8) * ASTRIDE + k0 + 4];
        }
    }

    // ---- Pass 1: per-token min of s = c2 - 2*dot ----
    float mn[2][2] = {{3.4e38f, 3.4e38f}, {3.4e38f, 3.4e38f}};
    #pragma unroll 1
    for (int c = 0; c < 32; c++) {
        u64 bp[4];
        #pragma unroll
        for (int ks = 0; ks < 4; ks++) bp[ks] = Bq[(c * 4 + ks) * 32 + lane];
        const float c2a = c2_s[c * 8 + tig * 2];
        const float c2b = c2_s[c * 8 + tig * 2 + 1];
        float s[2][4];
        calc_s(bp, afr, c2a, c2b, s);
        #pragma unroll
        for (int mt = 0; mt < 2; mt++) {
            mn[mt][0] = fminf(mn[mt][0], fminf(s[mt][0], s[mt][1]));
            mn[mt][1] = fminf(mn[mt][1], fminf(s[mt][2], s[mt][3]));
        }
    }
    #pragma unroll
    for (int mt = 0; mt < 2; mt++) {
        #pragma unroll
        for (int h = 0; h < 2; h++) {
            float v = mn[mt][h];
            v = fminf(v, __shfl_xor_sync(0xFFFFFFFFu, v, 1));
            v = fminf(v, __shfl_xor_sync(0xFFFFFFFFu, v, 2));
            mn[mt][h] = v;
        }
    }
    if (tig == 0) {
        best_s[m0 + gid]      = mn[0][0];
        best_s[m0 + gid + 8]  = mn[0][1];
        best_s[m0 + gid + 16] = mn[1][0];
        best_s[m0 + gid + 24] = mn[1][1];
    }
    __syncthreads();

    // ---- Threshold (rigorous tf32 bound, same formula that passed bit-exact) ----
    {
        thr_s[tid] = best_s[tid] + __fmaf_rn(sqrtf(x2), 1e-4f, 4e-5f);
        cand_cnt[tid] = 0;
    }
    __syncthreads();

    // ---- Pass 2: identical MMAs; flag candidates ----
    const float tA_lo = thr_s[m0 + gid];
    const float tA_hi = thr_s[m0 + gid + 8];
    const float tB_lo = thr_s[m0 + gid + 16];
    const float tB_hi = thr_s[m0 + gid + 24];
    #pragma unroll 1
    for (int c = 0; c < 32; c++) {
        u64 bp[4];
        #pragma unroll
        for (int ks = 0; ks < 4; ks++) bp[ks] = Bq[(c * 4 + ks) * 32 + lane];
        const int col0 = c * 8 + tig * 2;
        const float c2a = c2_s[col0];
        const float c2b = c2_s[col0 + 1];
        float s[2][4];
        calc_s(bp, afr, c2a, c2b, s);
        #pragma unroll
        for (int mt = 0; mt < 2; mt++) {
            const float tlo = mt ? tB_lo : tA_lo;
            const float thi = mt ? tB_hi : tA_hi;
            const int rlo = m0 + mt * 16 + gid;
            const int rhi = rlo + 8;
            if (s[mt][0] <= tlo) { int sl = atomicAdd(&cand_cnt[rlo], 1); if (sl < CANDCAP) cand[rlo * CANDCAP + sl] = col0; }
            if (s[mt][1] <= tlo) { int sl = atomicAdd(&cand_cnt[rlo], 1); if (sl < CANDCAP) cand[rlo * CANDCAP + sl] = col0 + 1; }
            if (s[mt][2] <= thi) { int sl = atomicAdd(&cand_cnt[rhi], 1); if (sl < CANDCAP) cand[rhi * CANDCAP + sl] = col0; }
            if (s[mt][3] <= thi) { int sl = atomicAdd(&cand_cnt[rhi], 1); if (sl < CANDCAP) cand[rhi * CANDCAP + sl] = col0 + 1; }
        }
    }
    __syncthreads();

    // ---- Exact recheck for token tid (R1 bit-exact d2; first-index ties) ----
    int bi = 0;
    {
        const int cnt = cand_cnt[tid];
        float bestE = 3.4e38f;
        if (cnt <= CANDCAP) {
            for (int i = 0; i < cnt; i++) {
                const int k = cand[tid * CANDCAP + i];
                const float4* qr = reinterpret_cast<const float4*>(cb + k * DIM);
                float dotx = 0.0f;
                #pragma unroll
                for (int jj = 0; jj < 8; jj++) {
                    float4 q4 = __ldg(qr + jj);
                    dotx = __fmaf_rn(xr[4*jj+0], q4.x, dotx);
                    dotx = __fmaf_rn(xr[4*jj+1], q4.y, dotx);
                    dotx = __fmaf_rn(xr[4*jj+2], q4.z, dotx);
                    dotx = __fmaf_rn(xr[4*jj+3], q4.w, dotx);
                }
                float d2 = __fadd_rn(__fadd_rn(x2, __fmul_rn(-2.0f, dotx)), c2_s[k]);
                if (d2 < bestE || (d2 == bestE && k < bi)) { bestE = d2; bi = k; }
            }
        } else {
            for (int k = 0; k < KCODES; k++) {
                const float4* qr = reinterpret_cast<const float4*>(cb + k * DIM);
                float dotx = 0.0f;
                #pragma unroll
                for (int jj = 0; jj < 8; jj++) {
                    float4 q4 = __ldg(qr + jj);
                    dotx = __fmaf_rn(xr[4*jj+0], q4.x, dotx);
                    dotx = __fmaf_rn(xr[4*jj+1], q4.y, dotx);
                    dotx = __fmaf_rn(xr[4*jj+2], q4.z, dotx);
                    dotx = __fmaf_rn(xr[4*jj+3], q4.w, dotx);
                }
                float d2 = __fadd_rn(__fadd_rn(x2, __fmul_rn(-2.0f, dotx)), c2_s[k]);
                if (d2 < bestE) { bestE = d2; bi = k; }
            }
        }
    }

    // ---- Epilogue: histogram + rotation-trick output ----
    atomicAdd(&hist[bi], 1.0f);
    {
        float qv[DIM];
        const float4* qrow = reinterpret_cast<const float4*>(cb + bi * DIM);
        #pragma unroll
        for (int j = 0; j < 8; j++) {
            float4 v = __ldg(qrow + j);
            qv[4*j+0] = v.x; qv[4*j+1] = v.y; qv[4*j+2] = v.z; qv[4*j+3] = v.w;
        }
        float q2 = 0.f, dotq = 0.f;
        #pragma unroll
        for (int d = 0; d < DIM; d++) {
            q2   = __fmaf_rn(qv[d], qv[d], q2);
            dotq = __fmaf_rn(xr[d], qv[d], dotq);
        }
        const float eps = 1e-6f;
        float inx = 1.0f / fmaxf(sqrtf(x2), eps);
        float inq = 1.0f / fmaxf(sqrtf(q2), eps);
        float u2  = x2 * inx * inx;
        float qh2 = q2 * inq * inq;
        float uq  = dotq * inx * inq;
        float w2  = u2 + qh2 + 2.0f * uq;
        float iw  = 1.0f / fmaxf(sqrtf(w2), eps);
        float ew  = (x2 * inx + dotq * inq) * iw;
        float eu  = x2 * inx;
        float a   = -2.0f * ew * iw;
        float s1  = 1.0f + a * inx;
        float s2  = (a + 2.0f * eu) * inq;

        float4* rp = reinterpret_cast<float4*>(out_rot + (tok0 + tid) * DIM);
        #pragma unroll
        for (int j = 0; j < 8; j++) {
            float4 v;
            v.x = xr[4*j+0] * s1 + qv[4*j+0] * s2;
            v.y = xr[4*j+1] * s1 + qv[4*j+1] * s2;
            v.z = xr[4*j+2] * s1 + qv[4*j+2] * s2;
            v.w = xr[4*j+3] * s1 + qv[4*j+3] * s2;
            rp[j] = v;
        }
        out_idx[tok0 + tid] = (float)bi;
    }

    // ---- Flush histogram ----
    __syncthreads();
    #pragma unroll
    for (int rr = 0; rr < 2; rr++)
        atomicAdd(&out_counts[tid + rr * TPB], hist[tid + rr * TPB]);
}

extern "C" void kernel_launch(void* const* d_in, const int* in_sizes, int n_in,
                              void* d_out, int out_size) {
    const float* x  = (const float*)d_in[0];
    const float* cb = (const float*)d_in[1];
    float* out = (float*)d_out;

    const int N = in_sizes[0] / DIM;            // 524288
    float* rot    = out;
    float* idx    = out + (size_t)N * DIM;
    float* counts = idx + N;

    const int dyn = 32768 + TPB * ASTRIDE * 4;  // Bq + As = 49664 B
    cudaFuncSetAttribute(vq_tc, cudaFuncAttributeMaxDynamicSharedMemorySize, dyn);
    vq_zero_counts<<<1, KCODES>>>(counts);
    vq_tc<<<NTILES, TPB, dyn>>>(x, cb, rot, idx, counts);
}